// round 4
// baseline (speedup 1.0000x reference)
#include <cuda_runtime.h>
#include <cstdint>

#define N_NODES 500000
#define N_EDGES 5000000
#define N_GRAPHS 5000
#define FEAT 7
#define STATE 16
#define ROUNDS 4

#define SCAN_CHUNK 1024
#define SCAN_T 256
#define SCAN_NB ((N_NODES + SCAN_CHUNK - 1) / SCAN_CHUNK)   // 489

// ---- scratch (__device__ globals; no allocs allowed) ----
__device__ float g_state[N_NODES * STATE];
__device__ float g_msg_a[N_NODES * STATE];
__device__ float g_msg_b[N_NODES * STATE];
__device__ int   g_cnt[N_NODES];
__device__ int   g_excl[N_NODES];
__device__ int   g_bsum[SCAN_NB];
__device__ int   g_ptr[N_NODES + 1];
__device__ int   g_rank[N_EDGES];
__device__ int   g_csr_src[N_EDGES];

// ================= CSR build =================
// zero counts + init out[] with bias (merged launch)
__global__ void init_kernel(const float* __restrict__ out_b, float* __restrict__ out) {
    int i = blockIdx.x * blockDim.x + threadIdx.x;
    if (i < N_NODES) g_cnt[i] = 0;
    if (i < N_GRAPHS) out[i] = out_b[0];
}

// histogram AND per-edge rank (atomic return value reused — no atomic in scatter)
__global__ void hist_kernel(const int* __restrict__ ei) {
    int e = blockIdx.x * blockDim.x + threadIdx.x;
    if (e < N_EDGES) g_rank[e] = atomicAdd(&g_cnt[ei[N_EDGES + e]], 1);
}

// block-local exclusive scan over chunks of 1024 (4 elems/thread)
__global__ void scan1_kernel() {
    __shared__ int sh[SCAN_T];
    int b = blockIdx.x, t = threadIdx.x;
    int base = b * SCAN_CHUNK + t * 4;
    int v[4];
#pragma unroll
    for (int k = 0; k < 4; k++) {
        int idx = base + k;
        v[k] = (idx < N_NODES) ? g_cnt[idx] : 0;
    }
    int s = v[0] + v[1] + v[2] + v[3];
    sh[t] = s;
    __syncthreads();
    for (int off = 1; off < SCAN_T; off <<= 1) {
        int x = (t >= off) ? sh[t - off] : 0;
        __syncthreads();
        sh[t] += x;
        __syncthreads();
    }
    int thread_excl = sh[t] - s;
    if (t == SCAN_T - 1) g_bsum[b] = sh[t];
    int run = thread_excl;
#pragma unroll
    for (int k = 0; k < 4; k++) {
        int idx = base + k;
        if (idx < N_NODES) g_excl[idx] = run;
        run += v[k];
    }
}

// single-block exclusive scan of block sums (SCAN_NB <= 512)
__global__ void scan2_kernel() {
    __shared__ int sh[512];
    int t = threadIdx.x;
    int orig = (t < SCAN_NB) ? g_bsum[t] : 0;
    sh[t] = orig;
    __syncthreads();
    for (int off = 1; off < 512; off <<= 1) {
        int x = (t >= off) ? sh[t - off] : 0;
        __syncthreads();
        sh[t] += x;
        __syncthreads();
    }
    if (t < SCAN_NB) g_bsum[t] = sh[t] - orig;   // exclusive
}

__global__ void scan3_kernel() {
    int i = blockIdx.x * blockDim.x + threadIdx.x;
    if (i < N_NODES) g_ptr[i] = g_excl[i] + g_bsum[i / SCAN_CHUNK];
    if (i == 0) g_ptr[N_NODES] = N_EDGES;
}

__global__ void scatter_kernel(const int* __restrict__ ei) {
    int e = blockIdx.x * blockDim.x + threadIdx.x;
    if (e >= N_EDGES) return;
    int s = ei[e];
    int d = ei[N_EDGES + e];
    g_csr_src[g_ptr[d] + g_rank[e]] = s;
}

// ============ input: state = relu(x@inW+b), msg0 = relu(state@msgW0+b0) ============
__global__ void input_kernel(const float* __restrict__ x,
                             const float* __restrict__ inW,
                             const float* __restrict__ inb,
                             const float* __restrict__ mW,
                             const float* __restrict__ mb) {
    __shared__ float sIW[FEAT * STATE];
    __shared__ float sIb[STATE];
    __shared__ float sMW[STATE * STATE];
    __shared__ float sMb[STATE];
    int t = threadIdx.x;
    if (t < FEAT * STATE) sIW[t] = inW[t];
    if (t < STATE) { sIb[t] = inb[t]; sMb[t] = mb[t]; }
    if (t < STATE * STATE) sMW[t] = mW[t];
    __syncthreads();

    int i = blockIdx.x * blockDim.x + t;
    if (i >= N_NODES) return;

    float xi[FEAT];
#pragma unroll
    for (int k = 0; k < FEAT; k++) xi[k] = x[(size_t)i * FEAT + k];

    float st[STATE];
#pragma unroll
    for (int j = 0; j < STATE; j++) {
        float acc = sIb[j];
#pragma unroll
        for (int k = 0; k < FEAT; k++) acc = fmaf(xi[k], sIW[k * STATE + j], acc);
        st[j] = fmaxf(acc, 0.f);
    }

    float4* sp = reinterpret_cast<float4*>(g_state + (size_t)i * STATE);
#pragma unroll
    for (int v = 0; v < 4; v++)
        sp[v] = make_float4(st[4 * v], st[4 * v + 1], st[4 * v + 2], st[4 * v + 3]);

    float m[STATE];
#pragma unroll
    for (int j = 0; j < STATE; j++) {
        float acc = sMb[j];
#pragma unroll
        for (int k = 0; k < STATE; k++) acc = fmaf(st[k], sMW[k * STATE + j], acc);
        m[j] = fmaxf(acc, 0.f);
    }
    float4* mp = reinterpret_cast<float4*>(g_msg_a + (size_t)i * STATE);
#pragma unroll
    for (int v = 0; v < 4; v++)
        mp[v] = make_float4(m[4 * v], m[4 * v + 1], m[4 * v + 2], m[4 * v + 3]);
}

// ============ fused round: 16 lanes per node, 4 edges in flight ============
// lane L within 16-lane group: edge slot = L>>2 (0..3), row quarter q = L&3.
// Per iteration the group consumes up to 8 edges (unroll 2).
#define WSTRIDE 17   // padded row stride for shared weights

__global__ void round_kernel(const float* __restrict__ updW,
                             const float* __restrict__ updb,
                             const float* __restrict__ msgW,   // unused if last
                             const float* __restrict__ msgb,
                             const float* __restrict__ msg_in,
                             float* __restrict__ msg_out,
                             int last,
                             const int* __restrict__ batch,
                             const float* __restrict__ outW,
                             float* __restrict__ out) {
    __shared__ float sUW[STATE * WSTRIDE];
    __shared__ float sMW[STATE * WSTRIDE];
    __shared__ float sUb[STATE];
    __shared__ float sMb[STATE];
    __shared__ float sOW[STATE];
    int t = threadIdx.x;
    if (t < STATE * STATE) {
        int r = t >> 4, c = t & 15;
        sUW[r * WSTRIDE + c] = updW[t];
        sMW[r * WSTRIDE + c] = last ? 0.f : msgW[t];
    }
    if (t < STATE) {
        sUb[t] = updb[t];
        sMb[t] = last ? 0.f : msgb[t];
        sOW[t] = last ? outW[t] : 0.f;
    }
    __syncthreads();

    int gtid = blockIdx.x * blockDim.x + t;
    int node = gtid >> 4;
    if (node >= N_NODES) return;
    int slot = (t >> 2) & 3;   // edge slot within group
    int q    = t & 3;          // row quarter

    int p0 = g_ptr[node];
    int p1 = g_ptr[node + 1];

    float4 acc0 = make_float4(0.f, 0.f, 0.f, 0.f);
    float4 acc1 = make_float4(0.f, 0.f, 0.f, 0.f);
    for (int j = p0; j < p1; j += 8) {
        int j0 = j + slot;
        int j1 = j + 4 + slot;
        if (j0 < p1) {
            int s = __ldg(&g_csr_src[j0]);
            float4 m = __ldg(reinterpret_cast<const float4*>(msg_in + (size_t)s * STATE) + q);
            acc0.x += m.x; acc0.y += m.y; acc0.z += m.z; acc0.w += m.w;
        }
        if (j1 < p1) {
            int s = __ldg(&g_csr_src[j1]);
            float4 m = __ldg(reinterpret_cast<const float4*>(msg_in + (size_t)s * STATE) + q);
            acc1.x += m.x; acc1.y += m.y; acc1.z += m.z; acc1.w += m.w;
        }
    }
    acc0.x += acc1.x; acc0.y += acc1.y; acc0.z += acc1.z; acc0.w += acc1.w;
    // fold edge slots: lanes with same q, different slot
    acc0.x += __shfl_xor_sync(0xFFFFFFFF, acc0.x, 4);
    acc0.y += __shfl_xor_sync(0xFFFFFFFF, acc0.y, 4);
    acc0.z += __shfl_xor_sync(0xFFFFFFFF, acc0.z, 4);
    acc0.w += __shfl_xor_sync(0xFFFFFFFF, acc0.w, 4);
    acc0.x += __shfl_xor_sync(0xFFFFFFFF, acc0.x, 8);
    acc0.y += __shfl_xor_sync(0xFFFFFFFF, acc0.y, 8);
    acc0.z += __shfl_xor_sync(0xFFFFFFFF, acc0.z, 8);
    acc0.w += __shfl_xor_sync(0xFFFFFFFF, acc0.w, 8);
    // now every lane holds agg quarter q

    // GEMV1: u = agg @ updW (partials over this lane's quarter, fold across q)
    const float* uw = sUW + (4 * q) * WSTRIDE;
    float u[STATE];
#pragma unroll
    for (int j = 0; j < STATE; j++)
        u[j] = fmaf(acc0.x, uw[j],
               fmaf(acc0.y, uw[WSTRIDE + j],
               fmaf(acc0.z, uw[2 * WSTRIDE + j],
                    acc0.w * uw[3 * WSTRIDE + j])));
#pragma unroll
    for (int j = 0; j < STATE; j++) {
        u[j] += __shfl_xor_sync(0xFFFFFFFF, u[j], 1);
        u[j] += __shfl_xor_sync(0xFFFFFFFF, u[j], 2);
    }

    // state quarter (64B row read by 16 lanes -> broadcast within line)
    float4 stv = __ldg(reinterpret_cast<const float4*>(g_state + (size_t)node * STATE) + q);
    float st[4];
    st[0] = stv.x + fmaxf(u[4 * q + 0] + sUb[4 * q + 0], 0.f);
    st[1] = stv.y + fmaxf(u[4 * q + 1] + sUb[4 * q + 1], 0.f);
    st[2] = stv.z + fmaxf(u[4 * q + 2] + sUb[4 * q + 2], 0.f);
    st[3] = stv.w + fmaxf(u[4 * q + 3] + sUb[4 * q + 3], 0.f);

    if (!last) {
        if (slot == 0)
            *(reinterpret_cast<float4*>(g_state + (size_t)node * STATE) + q) =
                make_float4(st[0], st[1], st[2], st[3]);
        // GEMV2: next message
        const float* mw = sMW + (4 * q) * WSTRIDE;
        float m[STATE];
#pragma unroll
        for (int j = 0; j < STATE; j++)
            m[j] = fmaf(st[0], mw[j],
                   fmaf(st[1], mw[WSTRIDE + j],
                   fmaf(st[2], mw[2 * WSTRIDE + j],
                        st[3] * mw[3 * WSTRIDE + j])));
#pragma unroll
        for (int j = 0; j < STATE; j++) {
            m[j] += __shfl_xor_sync(0xFFFFFFFF, m[j], 1);
            m[j] += __shfl_xor_sync(0xFFFFFFFF, m[j], 2);
        }
        if (slot == 0) {
            float4 mv;
            mv.x = fmaxf(m[4 * q + 0] + sMb[4 * q + 0], 0.f);
            mv.y = fmaxf(m[4 * q + 1] + sMb[4 * q + 1], 0.f);
            mv.z = fmaxf(m[4 * q + 2] + sMb[4 * q + 2], 0.f);
            mv.w = fmaxf(m[4 * q + 3] + sMb[4 * q + 3], 0.f);
            *(reinterpret_cast<float4*>(msg_out + (size_t)node * STATE) + q) = mv;
        }
    } else {
        // readout: dot(state, outW); fold across quarters, lane (slot==0,q==0) commits
        float dot = fmaf(st[0], sOW[4 * q + 0],
                    fmaf(st[1], sOW[4 * q + 1],
                    fmaf(st[2], sOW[4 * q + 2],
                         st[3] * sOW[4 * q + 3])));
        dot += __shfl_xor_sync(0xFFFFFFFF, dot, 1);
        dot += __shfl_xor_sync(0xFFFFFFFF, dot, 2);
        if ((t & 15) == 0) atomicAdd(&out[batch[node]], dot);
    }
}

extern "C" void kernel_launch(void* const* d_in, const int* in_sizes, int n_in,
                              void* d_out, int out_size) {
    const float* x     = (const float*)d_in[0];
    const int*   ei    = (const int*)d_in[1];
    const int*   batch = (const int*)d_in[2];
    const float* in_W  = (const float*)d_in[3];
    const float* in_b  = (const float*)d_in[4];
    const float* msg_W = (const float*)d_in[5];
    const float* msg_b = (const float*)d_in[6];
    const float* upd_W = (const float*)d_in[7];
    const float* upd_b = (const float*)d_in[8];
    const float* out_W = (const float*)d_in[9];
    const float* out_b = (const float*)d_in[10];
    float* out = (float*)d_out;

    const int TB = 256;
    int node_blocks = (N_NODES + TB - 1) / TB;
    int edge_blocks = (N_EDGES + TB - 1) / TB;
    long long rt = (long long)N_NODES * 16;
    int round_blocks = (int)((rt + TB - 1) / TB);

    // CSR build (by dst); hist returns per-edge rank, so scatter is atomic-free
    init_kernel<<<node_blocks, TB>>>(out_b, out);
    hist_kernel<<<edge_blocks, TB>>>(ei);
    scan1_kernel<<<SCAN_NB, SCAN_T>>>();
    scan2_kernel<<<1, 512>>>();
    scan3_kernel<<<node_blocks, TB>>>();
    scatter_kernel<<<edge_blocks, TB>>>(ei);

    // input + first message
    input_kernel<<<node_blocks, TB>>>(x, in_W, in_b, msg_W, msg_b);

    void* pa; void* pb;
    cudaGetSymbolAddress(&pa, g_msg_a);
    cudaGetSymbolAddress(&pb, g_msg_b);
    float* bufs[2] = {(float*)pa, (float*)pb};

    for (int r = 0; r < ROUNDS; r++) {
        int last = (r == ROUNDS - 1);
        const float* mW = last ? msg_W : (msg_W + (r + 1) * STATE * STATE);
        const float* mb = last ? msg_b : (msg_b + (r + 1) * STATE);
        round_kernel<<<round_blocks, TB>>>(
            upd_W + r * STATE * STATE, upd_b + r * STATE,
            mW, mb,
            bufs[r & 1], bufs[(r + 1) & 1],
            last, batch, out_W, out);
    }
}

// round 5
// speedup vs baseline: 2.0484x; 2.0484x over previous
#include <cuda_runtime.h>
#include <cstdint>

#define N_NODES 500000
#define N_EDGES 5000000
#define N_GRAPHS 5000
#define FEAT 7
#define STATE 16
#define ROUNDS 4

#define SCAN_CHUNK 1024
#define SCAN_T 256
#define SCAN_NB ((N_NODES + SCAN_CHUNK - 1) / SCAN_CHUNK)   // 489

// ---- scratch (__device__ globals; no allocs allowed) ----
__device__ float g_state[N_NODES * STATE];
__device__ float g_msg_a[N_NODES * STATE];
__device__ float g_msg_b[N_NODES * STATE];
__device__ int   g_cnt[N_NODES];
__device__ int   g_excl[N_NODES];
__device__ int   g_bsum[SCAN_NB];
__device__ int   g_ptr[N_NODES + 1];
__device__ int   g_rank[N_EDGES];
__device__ int   g_csr_src[N_EDGES];

// ================= CSR build =================
// zero counts + init out[] with bias (merged launch)
__global__ void init_kernel(const float* __restrict__ out_b, float* __restrict__ out) {
    int i = blockIdx.x * blockDim.x + threadIdx.x;
    if (i < N_NODES) g_cnt[i] = 0;
    if (i < N_GRAPHS) out[i] = out_b[0];
}

// histogram AND per-edge rank (atomic return value reused — no atomic in scatter)
__global__ void hist_kernel(const int* __restrict__ ei) {
    int e = blockIdx.x * blockDim.x + threadIdx.x;
    if (e < N_EDGES) g_rank[e] = atomicAdd(&g_cnt[__ldg(&ei[N_EDGES + e])], 1);
}

// block-local exclusive scan over chunks of 1024 (4 elems/thread)
__global__ void scan1_kernel() {
    __shared__ int sh[SCAN_T];
    int b = blockIdx.x, t = threadIdx.x;
    int base = b * SCAN_CHUNK + t * 4;
    int v[4];
#pragma unroll
    for (int k = 0; k < 4; k++) {
        int idx = base + k;
        v[k] = (idx < N_NODES) ? g_cnt[idx] : 0;
    }
    int s = v[0] + v[1] + v[2] + v[3];
    sh[t] = s;
    __syncthreads();
    for (int off = 1; off < SCAN_T; off <<= 1) {
        int x = (t >= off) ? sh[t - off] : 0;
        __syncthreads();
        sh[t] += x;
        __syncthreads();
    }
    int thread_excl = sh[t] - s;
    if (t == SCAN_T - 1) g_bsum[b] = sh[t];
    int run = thread_excl;
#pragma unroll
    for (int k = 0; k < 4; k++) {
        int idx = base + k;
        if (idx < N_NODES) g_excl[idx] = run;
        run += v[k];
    }
}

// single-block exclusive scan of block sums (SCAN_NB <= 512)
__global__ void scan2_kernel() {
    __shared__ int sh[512];
    int t = threadIdx.x;
    int orig = (t < SCAN_NB) ? g_bsum[t] : 0;
    sh[t] = orig;
    __syncthreads();
    for (int off = 1; off < 512; off <<= 1) {
        int x = (t >= off) ? sh[t - off] : 0;
        __syncthreads();
        sh[t] += x;
        __syncthreads();
    }
    if (t < SCAN_NB) g_bsum[t] = sh[t] - orig;   // exclusive
}

__global__ void scan3_kernel() {
    int i = blockIdx.x * blockDim.x + threadIdx.x;
    if (i < N_NODES) g_ptr[i] = g_excl[i] + g_bsum[i / SCAN_CHUNK];
    if (i == 0) g_ptr[N_NODES] = N_EDGES;
}

__global__ void scatter_kernel(const int* __restrict__ ei) {
    int e = blockIdx.x * blockDim.x + threadIdx.x;
    if (e >= N_EDGES) return;
    int s = __ldg(&ei[e]);
    int d = __ldg(&ei[N_EDGES + e]);
    g_csr_src[__ldg(&g_ptr[d]) + g_rank[e]] = s;
}

// ============ input: state = relu(x@inW+b), msg0 = relu(state@msgW0+b0) ============
__global__ void input_kernel(const float* __restrict__ x,
                             const float* __restrict__ inW,
                             const float* __restrict__ inb,
                             const float* __restrict__ mW,
                             const float* __restrict__ mb) {
    __shared__ float sIW[FEAT * STATE];
    __shared__ float sIb[STATE];
    __shared__ float sMW[STATE * STATE];
    __shared__ float sMb[STATE];
    int t = threadIdx.x;
    if (t < FEAT * STATE) sIW[t] = inW[t];
    if (t < STATE) { sIb[t] = inb[t]; sMb[t] = mb[t]; }
    if (t < STATE * STATE) sMW[t] = mW[t];
    __syncthreads();

    int i = blockIdx.x * blockDim.x + t;
    if (i >= N_NODES) return;

    float xi[FEAT];
#pragma unroll
    for (int k = 0; k < FEAT; k++) xi[k] = x[(size_t)i * FEAT + k];

    float st[STATE];
#pragma unroll
    for (int j = 0; j < STATE; j++) {
        float acc = sIb[j];
#pragma unroll
        for (int k = 0; k < FEAT; k++) acc = fmaf(xi[k], sIW[k * STATE + j], acc);
        st[j] = fmaxf(acc, 0.f);
    }

    float4* sp = reinterpret_cast<float4*>(g_state + (size_t)i * STATE);
#pragma unroll
    for (int v = 0; v < 4; v++)
        sp[v] = make_float4(st[4 * v], st[4 * v + 1], st[4 * v + 2], st[4 * v + 3]);

    float m[STATE];
#pragma unroll
    for (int j = 0; j < STATE; j++) {
        float acc = sMb[j];
#pragma unroll
        for (int k = 0; k < STATE; k++) acc = fmaf(st[k], sMW[k * STATE + j], acc);
        m[j] = fmaxf(acc, 0.f);
    }
    float4* mp = reinterpret_cast<float4*>(g_msg_a + (size_t)i * STATE);
#pragma unroll
    for (int v = 0; v < 4; v++)
        mp[v] = make_float4(m[4 * v], m[4 * v + 1], m[4 * v + 2], m[4 * v + 3]);
}

// ============ fused round: 4 lanes per node, unroll-4 gather ============
#define WSTRIDE 17   // padded row stride for shared weights (conflict-free across lanes)

__global__ void round_kernel(const float* __restrict__ updW,
                             const float* __restrict__ updb,
                             const float* __restrict__ msgW,   // unused if last
                             const float* __restrict__ msgb,
                             const float* __restrict__ msg_in,
                             float* __restrict__ msg_out,
                             int last,
                             const int* __restrict__ batch,
                             const float* __restrict__ outW,
                             float* __restrict__ out) {
    __shared__ float sUW[STATE * WSTRIDE];
    __shared__ float sMW[STATE * WSTRIDE];
    __shared__ float sUb[STATE];
    __shared__ float sMb[STATE];
    __shared__ float sOW[STATE];
    int t = threadIdx.x;
    if (t < STATE * STATE) {
        int r = t >> 4, c = t & 15;
        sUW[r * WSTRIDE + c] = updW[t];
        sMW[r * WSTRIDE + c] = last ? 0.f : msgW[t];
    }
    if (t < STATE) {
        sUb[t] = updb[t];
        sMb[t] = last ? 0.f : msgb[t];
        sOW[t] = last ? outW[t] : 0.f;
    }
    __syncthreads();

    int gtid = blockIdx.x * blockDim.x + t;
    int node = gtid >> 2;
    int lane = gtid & 3;
    if (node >= N_NODES) return;

    int p0 = g_ptr[node];
    int p1 = g_ptr[node + 1];

    // gather with 4 independent accumulators (4 loads in flight per lane)
    float4 a0 = make_float4(0.f, 0.f, 0.f, 0.f);
    float4 a1 = make_float4(0.f, 0.f, 0.f, 0.f);
    float4 a2 = make_float4(0.f, 0.f, 0.f, 0.f);
    float4 a3 = make_float4(0.f, 0.f, 0.f, 0.f);
    int j = p0;
    for (; j + 4 <= p1; j += 4) {
        int s0 = __ldg(&g_csr_src[j + 0]);
        int s1 = __ldg(&g_csr_src[j + 1]);
        int s2 = __ldg(&g_csr_src[j + 2]);
        int s3 = __ldg(&g_csr_src[j + 3]);
        float4 m0 = __ldg(reinterpret_cast<const float4*>(msg_in + (size_t)s0 * STATE) + lane);
        float4 m1 = __ldg(reinterpret_cast<const float4*>(msg_in + (size_t)s1 * STATE) + lane);
        float4 m2 = __ldg(reinterpret_cast<const float4*>(msg_in + (size_t)s2 * STATE) + lane);
        float4 m3 = __ldg(reinterpret_cast<const float4*>(msg_in + (size_t)s3 * STATE) + lane);
        a0.x += m0.x; a0.y += m0.y; a0.z += m0.z; a0.w += m0.w;
        a1.x += m1.x; a1.y += m1.y; a1.z += m1.z; a1.w += m1.w;
        a2.x += m2.x; a2.y += m2.y; a2.z += m2.z; a2.w += m2.w;
        a3.x += m3.x; a3.y += m3.y; a3.z += m3.z; a3.w += m3.w;
    }
    for (; j < p1; j++) {
        int s = __ldg(&g_csr_src[j]);
        float4 m = __ldg(reinterpret_cast<const float4*>(msg_in + (size_t)s * STATE) + lane);
        a0.x += m.x; a0.y += m.y; a0.z += m.z; a0.w += m.w;
    }
    float4 acc;
    acc.x = (a0.x + a1.x) + (a2.x + a3.x);
    acc.y = (a0.y + a1.y) + (a2.y + a3.y);
    acc.z = (a0.z + a1.z) + (a2.z + a3.z);
    acc.w = (a0.w + a1.w) + (a2.w + a3.w);

    // GEMV1 partials: u[j] over this lane's k-slice, fold across 4-lane group
    const float* uw = sUW + (4 * lane) * WSTRIDE;
    float u[STATE];
#pragma unroll
    for (int jj = 0; jj < STATE; jj++)
        u[jj] = fmaf(acc.x, uw[jj],
                fmaf(acc.y, uw[WSTRIDE + jj],
                fmaf(acc.z, uw[2 * WSTRIDE + jj],
                     acc.w * uw[3 * WSTRIDE + jj])));
#pragma unroll
    for (int jj = 0; jj < STATE; jj++) {
        u[jj] += __shfl_xor_sync(0xFFFFFFFF, u[jj], 1);
        u[jj] += __shfl_xor_sync(0xFFFFFFFF, u[jj], 2);
    }

    // state slice for this lane
    float4 stv = *(reinterpret_cast<const float4*>(g_state + (size_t)node * STATE) + lane);
    float st[4];
    st[0] = stv.x + fmaxf(u[4 * lane + 0] + sUb[4 * lane + 0], 0.f);
    st[1] = stv.y + fmaxf(u[4 * lane + 1] + sUb[4 * lane + 1], 0.f);
    st[2] = stv.z + fmaxf(u[4 * lane + 2] + sUb[4 * lane + 2], 0.f);
    st[3] = stv.w + fmaxf(u[4 * lane + 3] + sUb[4 * lane + 3], 0.f);

    if (!last) {
        *(reinterpret_cast<float4*>(g_state + (size_t)node * STATE) + lane) =
            make_float4(st[0], st[1], st[2], st[3]);
        // GEMV2: next message
        const float* mw = sMW + (4 * lane) * WSTRIDE;
        float m[STATE];
#pragma unroll
        for (int jj = 0; jj < STATE; jj++)
            m[jj] = fmaf(st[0], mw[jj],
                    fmaf(st[1], mw[WSTRIDE + jj],
                    fmaf(st[2], mw[2 * WSTRIDE + jj],
                         st[3] * mw[3 * WSTRIDE + jj])));
#pragma unroll
        for (int jj = 0; jj < STATE; jj++) {
            m[jj] += __shfl_xor_sync(0xFFFFFFFF, m[jj], 1);
            m[jj] += __shfl_xor_sync(0xFFFFFFFF, m[jj], 2);
        }
        float4 mv;
        mv.x = fmaxf(m[4 * lane + 0] + sMb[4 * lane + 0], 0.f);
        mv.y = fmaxf(m[4 * lane + 1] + sMb[4 * lane + 1], 0.f);
        mv.z = fmaxf(m[4 * lane + 2] + sMb[4 * lane + 2], 0.f);
        mv.w = fmaxf(m[4 * lane + 3] + sMb[4 * lane + 3], 0.f);
        *(reinterpret_cast<float4*>(msg_out + (size_t)node * STATE) + lane) = mv;
    } else {
        // readout: dot(state, outW) reduced across the 4 lanes
        float dot = fmaf(st[0], sOW[4 * lane + 0],
                    fmaf(st[1], sOW[4 * lane + 1],
                    fmaf(st[2], sOW[4 * lane + 2],
                         st[3] * sOW[4 * lane + 3])));
        dot += __shfl_xor_sync(0xFFFFFFFF, dot, 1);
        dot += __shfl_xor_sync(0xFFFFFFFF, dot, 2);
        if (lane == 0) atomicAdd(&out[batch[node]], dot);
    }
}

extern "C" void kernel_launch(void* const* d_in, const int* in_sizes, int n_in,
                              void* d_out, int out_size) {
    const float* x     = (const float*)d_in[0];
    const int*   ei    = (const int*)d_in[1];
    const int*   batch = (const int*)d_in[2];
    const float* in_W  = (const float*)d_in[3];
    const float* in_b  = (const float*)d_in[4];
    const float* msg_W = (const float*)d_in[5];
    const float* msg_b = (const float*)d_in[6];
    const float* upd_W = (const float*)d_in[7];
    const float* upd_b = (const float*)d_in[8];
    const float* out_W = (const float*)d_in[9];
    const float* out_b = (const float*)d_in[10];
    float* out = (float*)d_out;

    const int TB = 256;
    int node_blocks = (N_NODES + TB - 1) / TB;
    int edge_blocks = (N_EDGES + TB - 1) / TB;
    int round_blocks = (N_NODES * 4 + TB - 1) / TB;

    // CSR build (by dst); hist returns per-edge rank, so scatter is atomic-free
    init_kernel<<<node_blocks, TB>>>(out_b, out);
    hist_kernel<<<edge_blocks, TB>>>(ei);
    scan1_kernel<<<SCAN_NB, SCAN_T>>>();
    scan2_kernel<<<1, 512>>>();
    scan3_kernel<<<node_blocks, TB>>>();
    scatter_kernel<<<edge_blocks, TB>>>(ei);

    // input + first message
    input_kernel<<<node_blocks, TB>>>(x, in_W, in_b, msg_W, msg_b);

    void* pa; void* pb;
    cudaGetSymbolAddress(&pa, g_msg_a);
    cudaGetSymbolAddress(&pb, g_msg_b);
    float* bufs[2] = {(float*)pa, (float*)pb};

    for (int r = 0; r < ROUNDS; r++) {
        int last = (r == ROUNDS - 1);
        const float* mW = last ? msg_W : (msg_W + (r + 1) * STATE * STATE);
        const float* mb = last ? msg_b : (msg_b + (r + 1) * STATE);
        round_kernel<<<round_blocks, TB>>>(
            upd_W + r * STATE * STATE, upd_b + r * STATE,
            mW, mb,
            bufs[r & 1], bufs[(r + 1) & 1],
            last, batch, out_W, out);
    }
}

// round 6
// speedup vs baseline: 2.2590x; 1.1028x over previous
#include <cuda_runtime.h>
#include <cuda_fp16.h>
#include <cstdint>

#define N_NODES 500000
#define N_EDGES 5000000
#define N_GRAPHS 5000
#define FEAT 7
#define STATE 16
#define ROUNDS 4

#define SCAN_CHUNK 1024
#define SCAN_T 256
#define SCAN_NB ((N_NODES + SCAN_CHUNK - 1) / SCAN_CHUNK)   // 489

// ---- scratch (__device__ globals; no allocs allowed) ----
__device__ float  g_state[N_NODES * STATE];
__device__ __half g_msg_a[N_NODES * STATE];   // fp16 messages (16 MB each)
__device__ __half g_msg_b[N_NODES * STATE];
__device__ int    g_cnt[N_NODES];
__device__ int    g_excl[N_NODES];
__device__ int    g_bsum[SCAN_NB];
__device__ int    g_ptr[N_NODES + 1];
__device__ unsigned short g_rank[N_EDGES];
__device__ int    g_csr_src[N_EDGES];

// ================= CSR build =================
__global__ void init_kernel(const float* __restrict__ out_b, float* __restrict__ out) {
    int i = blockIdx.x * blockDim.x + threadIdx.x;
    if (i < N_NODES) g_cnt[i] = 0;
    if (i < N_GRAPHS) out[i] = out_b[0];
}

__global__ void hist_kernel(const int* __restrict__ ei) {
    int e = blockIdx.x * blockDim.x + threadIdx.x;
    if (e < N_EDGES)
        g_rank[e] = (unsigned short)atomicAdd(&g_cnt[__ldg(&ei[N_EDGES + e])], 1);
}

__global__ void scan1_kernel() {
    __shared__ int sh[SCAN_T];
    int b = blockIdx.x, t = threadIdx.x;
    int base = b * SCAN_CHUNK + t * 4;
    int v[4];
#pragma unroll
    for (int k = 0; k < 4; k++) {
        int idx = base + k;
        v[k] = (idx < N_NODES) ? g_cnt[idx] : 0;
    }
    int s = v[0] + v[1] + v[2] + v[3];
    sh[t] = s;
    __syncthreads();
    for (int off = 1; off < SCAN_T; off <<= 1) {
        int x = (t >= off) ? sh[t - off] : 0;
        __syncthreads();
        sh[t] += x;
        __syncthreads();
    }
    int thread_excl = sh[t] - s;
    if (t == SCAN_T - 1) g_bsum[b] = sh[t];
    int run = thread_excl;
#pragma unroll
    for (int k = 0; k < 4; k++) {
        int idx = base + k;
        if (idx < N_NODES) g_excl[idx] = run;
        run += v[k];
    }
}

__global__ void scan2_kernel() {
    __shared__ int sh[512];
    int t = threadIdx.x;
    int orig = (t < SCAN_NB) ? g_bsum[t] : 0;
    sh[t] = orig;
    __syncthreads();
    for (int off = 1; off < 512; off <<= 1) {
        int x = (t >= off) ? sh[t - off] : 0;
        __syncthreads();
        sh[t] += x;
        __syncthreads();
    }
    if (t < SCAN_NB) g_bsum[t] = sh[t] - orig;   // exclusive
}

__global__ void scan3_kernel() {
    int i = blockIdx.x * blockDim.x + threadIdx.x;
    if (i < N_NODES) g_ptr[i] = g_excl[i] + g_bsum[i / SCAN_CHUNK];
    if (i == 0) g_ptr[N_NODES] = N_EDGES;
}

__global__ void scatter_kernel(const int* __restrict__ ei) {
    int e = blockIdx.x * blockDim.x + threadIdx.x;
    if (e >= N_EDGES) return;
    int s = __ldg(&ei[e]);
    int d = __ldg(&ei[N_EDGES + e]);
    g_csr_src[__ldg(&g_ptr[d]) + (int)g_rank[e]] = s;
}

// ---- helpers ----
__device__ __forceinline__ void store_msg_quarter(__half* dst, float a, float b, float c, float d) {
    __half2 h01 = __floats2half2_rn(a, b);
    __half2 h23 = __floats2half2_rn(c, d);
    uint2 raw;
    raw.x = *reinterpret_cast<unsigned int*>(&h01);
    raw.y = *reinterpret_cast<unsigned int*>(&h23);
    *reinterpret_cast<uint2*>(dst) = raw;
}

// ============ input: state = relu(x@inW+b), msg0 = relu(state@msgW0+b0) ============
__global__ void input_kernel(const float* __restrict__ x,
                             const float* __restrict__ inW,
                             const float* __restrict__ inb,
                             const float* __restrict__ mW,
                             const float* __restrict__ mb) {
    __shared__ float sIW[FEAT * STATE];
    __shared__ float sIb[STATE];
    __shared__ float sMW[STATE * STATE];
    __shared__ float sMb[STATE];
    int t = threadIdx.x;
    if (t < FEAT * STATE) sIW[t] = inW[t];
    if (t < STATE) { sIb[t] = inb[t]; sMb[t] = mb[t]; }
    if (t < STATE * STATE) sMW[t] = mW[t];
    __syncthreads();

    int i = blockIdx.x * blockDim.x + t;
    if (i >= N_NODES) return;

    float xi[FEAT];
#pragma unroll
    for (int k = 0; k < FEAT; k++) xi[k] = x[(size_t)i * FEAT + k];

    float st[STATE];
#pragma unroll
    for (int j = 0; j < STATE; j++) {
        float acc = sIb[j];
#pragma unroll
        for (int k = 0; k < FEAT; k++) acc = fmaf(xi[k], sIW[k * STATE + j], acc);
        st[j] = fmaxf(acc, 0.f);
    }

    float4* sp = reinterpret_cast<float4*>(g_state + (size_t)i * STATE);
#pragma unroll
    for (int v = 0; v < 4; v++)
        sp[v] = make_float4(st[4 * v], st[4 * v + 1], st[4 * v + 2], st[4 * v + 3]);

    float m[STATE];
#pragma unroll
    for (int j = 0; j < STATE; j++) {
        float acc = sMb[j];
#pragma unroll
        for (int k = 0; k < STATE; k++) acc = fmaf(st[k], sMW[k * STATE + j], acc);
        m[j] = fmaxf(acc, 0.f);
    }
    __half* mp = g_msg_a + (size_t)i * STATE;
#pragma unroll
    for (int v = 0; v < 4; v++)
        store_msg_quarter(mp + 4 * v, m[4 * v], m[4 * v + 1], m[4 * v + 2], m[4 * v + 3]);
}

// ============ fused round: 4 lanes per node, unroll-4 fp16 gather ============
#define WSTRIDE 17   // padded row stride for shared weights

__device__ __forceinline__ void acc_msg(const __half* __restrict__ msg_in,
                                        int s, int lane,
                                        float& ax, float& ay, float& az, float& aw) {
    uint2 raw = __ldg(reinterpret_cast<const uint2*>(msg_in + (size_t)s * STATE + 4 * lane));
    __half2 h01 = *reinterpret_cast<__half2*>(&raw.x);
    __half2 h23 = *reinterpret_cast<__half2*>(&raw.y);
    float2 f01 = __half22float2(h01);
    float2 f23 = __half22float2(h23);
    ax += f01.x; ay += f01.y; az += f23.x; aw += f23.y;
}

__global__ void round_kernel(const float* __restrict__ updW,
                             const float* __restrict__ updb,
                             const float* __restrict__ msgW,   // unused if last
                             const float* __restrict__ msgb,
                             const __half* __restrict__ msg_in,
                             __half* __restrict__ msg_out,
                             int last,
                             const int* __restrict__ batch,
                             const float* __restrict__ outW,
                             float* __restrict__ out) {
    __shared__ float sUW[STATE * WSTRIDE];
    __shared__ float sMW[STATE * WSTRIDE];
    __shared__ float sUb[STATE];
    __shared__ float sMb[STATE];
    __shared__ float sOW[STATE];
    int t = threadIdx.x;
    if (t < STATE * STATE) {
        int r = t >> 4, c = t & 15;
        sUW[r * WSTRIDE + c] = updW[t];
        sMW[r * WSTRIDE + c] = last ? 0.f : msgW[t];
    }
    if (t < STATE) {
        sUb[t] = updb[t];
        sMb[t] = last ? 0.f : msgb[t];
        sOW[t] = last ? outW[t] : 0.f;
    }
    __syncthreads();

    int gtid = blockIdx.x * blockDim.x + t;
    int node = gtid >> 2;
    int lane = gtid & 3;
    if (node >= N_NODES) return;

    int p0 = g_ptr[node];
    int p1 = g_ptr[node + 1];

    // 4 independent fp32 accumulator sets, fp16 loads (8B per lane per edge)
    float a0x = 0.f, a0y = 0.f, a0z = 0.f, a0w = 0.f;
    float a1x = 0.f, a1y = 0.f, a1z = 0.f, a1w = 0.f;
    float a2x = 0.f, a2y = 0.f, a2z = 0.f, a2w = 0.f;
    float a3x = 0.f, a3y = 0.f, a3z = 0.f, a3w = 0.f;
    int j = p0;
    for (; j + 4 <= p1; j += 4) {
        int s0 = __ldg(&g_csr_src[j + 0]);
        int s1 = __ldg(&g_csr_src[j + 1]);
        int s2 = __ldg(&g_csr_src[j + 2]);
        int s3 = __ldg(&g_csr_src[j + 3]);
        acc_msg(msg_in, s0, lane, a0x, a0y, a0z, a0w);
        acc_msg(msg_in, s1, lane, a1x, a1y, a1z, a1w);
        acc_msg(msg_in, s2, lane, a2x, a2y, a2z, a2w);
        acc_msg(msg_in, s3, lane, a3x, a3y, a3z, a3w);
    }
    for (; j < p1; j++) {
        int s = __ldg(&g_csr_src[j]);
        acc_msg(msg_in, s, lane, a0x, a0y, a0z, a0w);
    }
    float accx = (a0x + a1x) + (a2x + a3x);
    float accy = (a0y + a1y) + (a2y + a3y);
    float accz = (a0z + a1z) + (a2z + a3z);
    float accw = (a0w + a1w) + (a2w + a3w);

    // GEMV1 partials over this lane's k-slice, fold across 4-lane group
    const float* uw = sUW + (4 * lane) * WSTRIDE;
    float u[STATE];
#pragma unroll
    for (int jj = 0; jj < STATE; jj++)
        u[jj] = fmaf(accx, uw[jj],
                fmaf(accy, uw[WSTRIDE + jj],
                fmaf(accz, uw[2 * WSTRIDE + jj],
                     accw * uw[3 * WSTRIDE + jj])));
#pragma unroll
    for (int jj = 0; jj < STATE; jj++) {
        u[jj] += __shfl_xor_sync(0xFFFFFFFF, u[jj], 1);
        u[jj] += __shfl_xor_sync(0xFFFFFFFF, u[jj], 2);
    }

    // state slice (fp32)
    float4 stv = *(reinterpret_cast<const float4*>(g_state + (size_t)node * STATE) + lane);
    float st[4];
    st[0] = stv.x + fmaxf(u[4 * lane + 0] + sUb[4 * lane + 0], 0.f);
    st[1] = stv.y + fmaxf(u[4 * lane + 1] + sUb[4 * lane + 1], 0.f);
    st[2] = stv.z + fmaxf(u[4 * lane + 2] + sUb[4 * lane + 2], 0.f);
    st[3] = stv.w + fmaxf(u[4 * lane + 3] + sUb[4 * lane + 3], 0.f);

    if (!last) {
        *(reinterpret_cast<float4*>(g_state + (size_t)node * STATE) + lane) =
            make_float4(st[0], st[1], st[2], st[3]);
        // GEMV2: next message
        const float* mw = sMW + (4 * lane) * WSTRIDE;
        float m[STATE];
#pragma unroll
        for (int jj = 0; jj < STATE; jj++)
            m[jj] = fmaf(st[0], mw[jj],
                    fmaf(st[1], mw[WSTRIDE + jj],
                    fmaf(st[2], mw[2 * WSTRIDE + jj],
                         st[3] * mw[3 * WSTRIDE + jj])));
#pragma unroll
        for (int jj = 0; jj < STATE; jj++) {
            m[jj] += __shfl_xor_sync(0xFFFFFFFF, m[jj], 1);
            m[jj] += __shfl_xor_sync(0xFFFFFFFF, m[jj], 2);
        }
        store_msg_quarter(msg_out + (size_t)node * STATE + 4 * lane,
                          fmaxf(m[4 * lane + 0] + sMb[4 * lane + 0], 0.f),
                          fmaxf(m[4 * lane + 1] + sMb[4 * lane + 1], 0.f),
                          fmaxf(m[4 * lane + 2] + sMb[4 * lane + 2], 0.f),
                          fmaxf(m[4 * lane + 3] + sMb[4 * lane + 3], 0.f));
    } else {
        float dot = fmaf(st[0], sOW[4 * lane + 0],
                    fmaf(st[1], sOW[4 * lane + 1],
                    fmaf(st[2], sOW[4 * lane + 2],
                         st[3] * sOW[4 * lane + 3])));
        dot += __shfl_xor_sync(0xFFFFFFFF, dot, 1);
        dot += __shfl_xor_sync(0xFFFFFFFF, dot, 2);
        if (lane == 0) atomicAdd(&out[batch[node]], dot);
    }
}

extern "C" void kernel_launch(void* const* d_in, const int* in_sizes, int n_in,
                              void* d_out, int out_size) {
    const float* x     = (const float*)d_in[0];
    const int*   ei    = (const int*)d_in[1];
    const int*   batch = (const int*)d_in[2];
    const float* in_W  = (const float*)d_in[3];
    const float* in_b  = (const float*)d_in[4];
    const float* msg_W = (const float*)d_in[5];
    const float* msg_b = (const float*)d_in[6];
    const float* upd_W = (const float*)d_in[7];
    const float* upd_b = (const float*)d_in[8];
    const float* out_W = (const float*)d_in[9];
    const float* out_b = (const float*)d_in[10];
    float* out = (float*)d_out;

    const int TB = 256;
    int node_blocks = (N_NODES + TB - 1) / TB;
    int edge_blocks = (N_EDGES + TB - 1) / TB;
    int round_blocks = (N_NODES * 4 + TB - 1) / TB;

    init_kernel<<<node_blocks, TB>>>(out_b, out);
    hist_kernel<<<edge_blocks, TB>>>(ei);
    scan1_kernel<<<SCAN_NB, SCAN_T>>>();
    scan2_kernel<<<1, 512>>>();
    scan3_kernel<<<node_blocks, TB>>>();
    scatter_kernel<<<edge_blocks, TB>>>(ei);

    input_kernel<<<node_blocks, TB>>>(x, in_W, in_b, msg_W, msg_b);

    void* pa; void* pb;
    cudaGetSymbolAddress(&pa, g_msg_a);
    cudaGetSymbolAddress(&pb, g_msg_b);
    __half* bufs[2] = {(__half*)pa, (__half*)pb};

    for (int r = 0; r < ROUNDS; r++) {
        int last = (r == ROUNDS - 1);
        const float* mW = last ? msg_W : (msg_W + (r + 1) * STATE * STATE);
        const float* mb = last ? msg_b : (msg_b + (r + 1) * STATE);
        round_kernel<<<round_blocks, TB>>>(
            upd_W + r * STATE * STATE, upd_b + r * STATE,
            mW, mb,
            bufs[r & 1], bufs[(r + 1) & 1],
            last, batch, out_W, out);
    }
}

// round 7
// speedup vs baseline: 2.6568x; 1.1761x over previous
#include <cuda_runtime.h>
#include <cuda_fp16.h>
#include <cstdint>

#define N_NODES 500000
#define N_EDGES 5000000
#define N_GRAPHS 5000
#define FEAT 7
#define STATE 16
#define ROUNDS 4

#define SCAN_CHUNK 1024
#define SCAN_T 256
#define SCAN_NB ((N_NODES + SCAN_CHUNK - 1) / SCAN_CHUNK)   // 489

// ---- scratch (__device__ globals; no allocs allowed) ----
__device__ float  g_state[N_NODES * STATE];
__device__ __half g_msg_a[N_NODES * STATE];   // fp16 messages (16 MB each)
__device__ __half g_msg_b[N_NODES * STATE];
__device__ int    g_cnt[N_NODES];
__device__ int    g_excl[N_NODES];
__device__ int    g_bsum[SCAN_NB];
__device__ int    g_ptr[N_NODES + 1];
__device__ unsigned short g_rank[N_EDGES];
__device__ int    g_csr_src[N_EDGES];

// ================= CSR build =================
__global__ void init_kernel(const float* __restrict__ out_b, float* __restrict__ out) {
    int i = blockIdx.x * blockDim.x + threadIdx.x;
    if (i < N_NODES) g_cnt[i] = 0;
    if (i < N_GRAPHS) out[i] = out_b[0];
}

__global__ void hist_kernel(const int* __restrict__ ei) {
    int e = blockIdx.x * blockDim.x + threadIdx.x;
    if (e < N_EDGES)
        g_rank[e] = (unsigned short)atomicAdd(&g_cnt[__ldg(&ei[N_EDGES + e])], 1);
}

__global__ void scan1_kernel() {
    __shared__ int sh[SCAN_T];
    int b = blockIdx.x, t = threadIdx.x;
    int base = b * SCAN_CHUNK + t * 4;
    int v[4];
#pragma unroll
    for (int k = 0; k < 4; k++) {
        int idx = base + k;
        v[k] = (idx < N_NODES) ? g_cnt[idx] : 0;
    }
    int s = v[0] + v[1] + v[2] + v[3];
    sh[t] = s;
    __syncthreads();
    for (int off = 1; off < SCAN_T; off <<= 1) {
        int x = (t >= off) ? sh[t - off] : 0;
        __syncthreads();
        sh[t] += x;
        __syncthreads();
    }
    int thread_excl = sh[t] - s;
    if (t == SCAN_T - 1) g_bsum[b] = sh[t];
    int run = thread_excl;
#pragma unroll
    for (int k = 0; k < 4; k++) {
        int idx = base + k;
        if (idx < N_NODES) g_excl[idx] = run;
        run += v[k];
    }
}

__global__ void scan2_kernel() {
    __shared__ int sh[512];
    int t = threadIdx.x;
    int orig = (t < SCAN_NB) ? g_bsum[t] : 0;
    sh[t] = orig;
    __syncthreads();
    for (int off = 1; off < 512; off <<= 1) {
        int x = (t >= off) ? sh[t - off] : 0;
        __syncthreads();
        sh[t] += x;
        __syncthreads();
    }
    if (t < SCAN_NB) g_bsum[t] = sh[t] - orig;   // exclusive
}

__global__ void scan3_kernel() {
    int i = blockIdx.x * blockDim.x + threadIdx.x;
    if (i < N_NODES) g_ptr[i] = g_excl[i] + g_bsum[i / SCAN_CHUNK];
    if (i == 0) g_ptr[N_NODES] = N_EDGES;
}

__global__ void scatter_kernel(const int* __restrict__ ei) {
    int e = blockIdx.x * blockDim.x + threadIdx.x;
    if (e >= N_EDGES) return;
    int s = __ldg(&ei[e]);
    int d = __ldg(&ei[N_EDGES + e]);
    g_csr_src[__ldg(&g_ptr[d]) + (int)g_rank[e]] = s;
}

// ---- helpers ----
__device__ __forceinline__ void store_msg_row(__half* dst, const float* m) {
    uint4 raw;
    __half2 h;
    h = __floats2half2_rn(m[0], m[1]);  raw.x = *reinterpret_cast<unsigned int*>(&h);
    h = __floats2half2_rn(m[2], m[3]);  raw.x |= 0;  // keep simple packing below
    // pack 16 halves into uint4 x2
    unsigned int w[8];
#pragma unroll
    for (int v = 0; v < 8; v++) {
        __half2 hh = __floats2half2_rn(m[2 * v], m[2 * v + 1]);
        w[v] = *reinterpret_cast<unsigned int*>(&hh);
    }
    uint4 lo = make_uint4(w[0], w[1], w[2], w[3]);
    uint4 hi = make_uint4(w[4], w[5], w[6], w[7]);
    reinterpret_cast<uint4*>(dst)[0] = lo;
    reinterpret_cast<uint4*>(dst)[1] = hi;
}

__device__ __forceinline__ void acc_row(uint4 lo, uint4 hi, float* acc) {
    const unsigned int w[8] = {lo.x, lo.y, lo.z, lo.w, hi.x, hi.y, hi.z, hi.w};
#pragma unroll
    for (int v = 0; v < 8; v++) {
        __half2 hh = *reinterpret_cast<const __half2*>(&w[v]);
        float2 f = __half22float2(hh);
        acc[2 * v] += f.x;
        acc[2 * v + 1] += f.y;
    }
}

// ============ input: state = relu(x@inW+b), msg0 = relu(state@msgW0+b0) ============
__global__ void input_kernel(const float* __restrict__ x,
                             const float* __restrict__ inW,
                             const float* __restrict__ inb,
                             const float* __restrict__ mW,
                             const float* __restrict__ mb) {
    __shared__ float sIW[FEAT * STATE];
    __shared__ float sIb[STATE];
    __shared__ float sMW[STATE * STATE];
    __shared__ float sMb[STATE];
    int t = threadIdx.x;
    if (t < FEAT * STATE) sIW[t] = inW[t];
    if (t < STATE) { sIb[t] = inb[t]; sMb[t] = mb[t]; }
    if (t < STATE * STATE) sMW[t] = mW[t];
    __syncthreads();

    int i = blockIdx.x * blockDim.x + t;
    if (i >= N_NODES) return;

    float xi[FEAT];
#pragma unroll
    for (int k = 0; k < FEAT; k++) xi[k] = x[(size_t)i * FEAT + k];

    float st[STATE];
#pragma unroll
    for (int j = 0; j < STATE; j++) {
        float acc = sIb[j];
#pragma unroll
        for (int k = 0; k < FEAT; k++) acc = fmaf(xi[k], sIW[k * STATE + j], acc);
        st[j] = fmaxf(acc, 0.f);
    }

    float4* sp = reinterpret_cast<float4*>(g_state + (size_t)i * STATE);
#pragma unroll
    for (int v = 0; v < 4; v++)
        sp[v] = make_float4(st[4 * v], st[4 * v + 1], st[4 * v + 2], st[4 * v + 3]);

    float m[STATE];
#pragma unroll
    for (int j = 0; j < STATE; j++) {
        float acc = sMb[j];
#pragma unroll
        for (int k = 0; k < STATE; k++) acc = fmaf(st[k], sMW[k * STATE + j], acc);
        m[j] = fmaxf(acc, 0.f);
    }
    store_msg_row(g_msg_a + (size_t)i * STATE, m);
}

// ============ fused round: 1 thread per node, unroll-4 fp16 gather ============
__global__ __launch_bounds__(256) void round_kernel(
                             const float* __restrict__ updW,
                             const float* __restrict__ updb,
                             const float* __restrict__ msgW,   // unused if last
                             const float* __restrict__ msgb,
                             const __half* __restrict__ msg_in,
                             __half* __restrict__ msg_out,
                             int last,
                             const int* __restrict__ batch,
                             const float* __restrict__ outW,
                             float* __restrict__ out) {
    __shared__ float sUW[STATE * STATE];
    __shared__ float sMW[STATE * STATE];
    __shared__ float sUb[STATE];
    __shared__ float sMb[STATE];
    __shared__ float sOW[STATE];
    int t = threadIdx.x;
    if (t < STATE * STATE) {
        sUW[t] = updW[t];
        sMW[t] = last ? 0.f : msgW[t];
    }
    if (t < STATE) {
        sUb[t] = updb[t];
        sMb[t] = last ? 0.f : msgb[t];
        sOW[t] = last ? outW[t] : 0.f;
    }
    __syncthreads();

    int node = blockIdx.x * blockDim.x + t;
    if (node >= N_NODES) return;

    int p0 = g_ptr[node];
    int p1 = g_ptr[node + 1];

    float acc[STATE];
#pragma unroll
    for (int k = 0; k < STATE; k++) acc[k] = 0.f;

    const uint4* mi = reinterpret_cast<const uint4*>(msg_in);

    int j = p0;
    for (; j + 4 <= p1; j += 4) {
        int s0 = __ldg(&g_csr_src[j + 0]);
        int s1 = __ldg(&g_csr_src[j + 1]);
        int s2 = __ldg(&g_csr_src[j + 2]);
        int s3 = __ldg(&g_csr_src[j + 3]);
        // 8 independent 16B loads in flight
        uint4 l0 = __ldg(mi + 2 * (size_t)s0);
        uint4 h0 = __ldg(mi + 2 * (size_t)s0 + 1);
        uint4 l1 = __ldg(mi + 2 * (size_t)s1);
        uint4 h1 = __ldg(mi + 2 * (size_t)s1 + 1);
        uint4 l2 = __ldg(mi + 2 * (size_t)s2);
        uint4 h2 = __ldg(mi + 2 * (size_t)s2 + 1);
        uint4 l3 = __ldg(mi + 2 * (size_t)s3);
        uint4 h3 = __ldg(mi + 2 * (size_t)s3 + 1);
        acc_row(l0, h0, acc);
        acc_row(l1, h1, acc);
        acc_row(l2, h2, acc);
        acc_row(l3, h3, acc);
    }
    for (; j < p1; j++) {
        int s = __ldg(&g_csr_src[j]);
        uint4 lo = __ldg(mi + 2 * (size_t)s);
        uint4 hi = __ldg(mi + 2 * (size_t)s + 1);
        acc_row(lo, hi, acc);
    }

    // load state (2x float4)
    float st[STATE];
    float4* sp = reinterpret_cast<float4*>(g_state + (size_t)node * STATE);
#pragma unroll
    for (int v = 0; v < 4; v++) {
        float4 f = sp[v];
        st[4 * v] = f.x; st[4 * v + 1] = f.y; st[4 * v + 2] = f.z; st[4 * v + 3] = f.w;
    }

    // state += relu(agg @ updW + updb)   (uniform shared reads -> broadcast)
#pragma unroll
    for (int jj = 0; jj < STATE; jj++) {
        float u = sUb[jj];
#pragma unroll
        for (int k = 0; k < STATE; k++) u = fmaf(acc[k], sUW[k * STATE + jj], u);
        st[jj] += fmaxf(u, 0.f);
    }

    if (!last) {
#pragma unroll
        for (int v = 0; v < 4; v++)
            sp[v] = make_float4(st[4 * v], st[4 * v + 1], st[4 * v + 2], st[4 * v + 3]);
        float m[STATE];
#pragma unroll
        for (int jj = 0; jj < STATE; jj++) {
            float a2 = sMb[jj];
#pragma unroll
            for (int k = 0; k < STATE; k++) a2 = fmaf(st[k], sMW[k * STATE + jj], a2);
            m[jj] = fmaxf(a2, 0.f);
        }
        store_msg_row(msg_out + (size_t)node * STATE, m);
    } else {
        float dot = 0.f;
#pragma unroll
        for (int k = 0; k < STATE; k++) dot = fmaf(st[k], sOW[k], dot);
        atomicAdd(&out[batch[node]], dot);
    }
}

extern "C" void kernel_launch(void* const* d_in, const int* in_sizes, int n_in,
                              void* d_out, int out_size) {
    const float* x     = (const float*)d_in[0];
    const int*   ei    = (const int*)d_in[1];
    const int*   batch = (const int*)d_in[2];
    const float* in_W  = (const float*)d_in[3];
    const float* in_b  = (const float*)d_in[4];
    const float* msg_W = (const float*)d_in[5];
    const float* msg_b = (const float*)d_in[6];
    const float* upd_W = (const float*)d_in[7];
    const float* upd_b = (const float*)d_in[8];
    const float* out_W = (const float*)d_in[9];
    const float* out_b = (const float*)d_in[10];
    float* out = (float*)d_out;

    const int TB = 256;
    int node_blocks = (N_NODES + TB - 1) / TB;
    int edge_blocks = (N_EDGES + TB - 1) / TB;

    init_kernel<<<node_blocks, TB>>>(out_b, out);
    hist_kernel<<<edge_blocks, TB>>>(ei);
    scan1_kernel<<<SCAN_NB, SCAN_T>>>();
    scan2_kernel<<<1, 512>>>();
    scan3_kernel<<<node_blocks, TB>>>();
    scatter_kernel<<<edge_blocks, TB>>>(ei);

    input_kernel<<<node_blocks, TB>>>(x, in_W, in_b, msg_W, msg_b);

    void* pa; void* pb;
    cudaGetSymbolAddress(&pa, g_msg_a);
    cudaGetSymbolAddress(&pb, g_msg_b);
    __half* bufs[2] = {(__half*)pa, (__half*)pb};

    for (int r = 0; r < ROUNDS; r++) {
        int last = (r == ROUNDS - 1);
        const float* mW = last ? msg_W : (msg_W + (r + 1) * STATE * STATE);
        const float* mb = last ? msg_b : (msg_b + (r + 1) * STATE);
        round_kernel<<<node_blocks, TB>>>(
            upd_W + r * STATE * STATE, upd_b + r * STATE,
            mW, mb,
            bufs[r & 1], bufs[(r + 1) & 1],
            last, batch, out_W, out);
    }
}